// round 7
// baseline (speedup 1.0000x reference)
#include <cuda_runtime.h>
#include <cuda_bf16.h>

// loss[s] = -(1/496)*[ sum_i x_i*(31-i) - sum_{i<j} ln(e_i+e_j) + 0.0005*sum_i x_i^2*(31-2i) ]
// via log_sigmoid(x_i - x_j) == x_i - ln(e^{x_i} + e^{x_j}).
//
// sum_{pairs} ln = ln(prod): per lane, ONE renorm-free 16-term fp32 product
// (e prescaled by 2^-2 so the exponent stays within +-112), one lg2 at the
// end; the 2^-2 scaling folds into a per-lane additive constant.
//
// PERSISTENT: 512 CTAs x 128 thr; each warp runs 4 iterations of 4 segments
// with next-iteration loads prefetched before the pair core, so the DRAM
// round-trip is paid once, not per segment-group.

static constexpr float INV_PAIRS = 1.0f / 496.0f;
static constexpr float LN2  = 0.69314718055994530942f;
static constexpr float L2E  = 1.44269504088896340736f;
static constexpr int   WPB   = 4;     // warps per block (128 thr)
static constexpr int   BLKS  = 512;
static constexpr int   ITERS = 4;     // 512*4 warps * 4 seg * 4 iters = 32768

typedef unsigned int u32;

__device__ __forceinline__ float ex2(float x) {
    float r; asm("ex2.approx.f32 %0,%1;" : "=f"(r) : "f"(x)); return r;
}
__device__ __forceinline__ float lg2(float x) {
    float r; asm("lg2.approx.f32 %0,%1;" : "=f"(r) : "f"(x)); return r;
}
// log2 of a renorm-free product: (E-127) + lg2(mantissa in [1,2)).
__device__ __forceinline__ float log2p(float p) {
    u32 b = __float_as_uint(p);
    float m = __uint_as_float((b & 0x007FFFFFu) | 0x3F800000u);
    return (float)((int)(b >> 23) - 127) + lg2(m);
}

__global__ __launch_bounds__(WPB * 32, 1)
void rmloss_kernel(const float* __restrict__ logits,
                   float4* __restrict__ out,
                   int n_seg)
{
    __shared__ float2 r01[WPB][64];   // interleaved (segA, segB), duplicated ring
    __shared__ float2 r23[WPB][64];   // interleaved (segC, segD), duplicated ring

    const int w    = threadIdx.x >> 5;
    const int lane = threadIdx.x & 31;
    const int gw   = blockIdx.x * WPB + w;          // 0..2047
    const int nw   = BLKS * WPB;                     // 2048 warps total

    // Per-lane constants (all scale factors folded in).
    const float CL  = (float)(31 - lane)     * (-INV_PAIRS);
    const float CQ  = (float)(31 - 2 * lane) * (-0.0005f * INV_PAIRS);
    const float CLN = LN2 * INV_PAIRS;
    // 2^-2 prescale correction: lane<16 has 16 pair terms, lane>=16 has 15.
    const float KPS = CLN * ((lane < 16) ? 32.0f : 30.0f);
    const bool  lo16 = (lane < 16);

    // Prefetch iteration 0.
    const float* base0 = logits + (size_t)gw * 128 + lane;
    float x0 = base0[0], x1 = base0[32], x2 = base0[64], x3 = base0[96];

    #pragma unroll
    for (int it = 0; it < ITERS; ++it) {
        // es = exp(x) * 2^-2  (prescale keeps 16-term product in range)
        const float e0 = ex2(fmaf(x0, L2E, -2.0f));
        const float e1 = ex2(fmaf(x1, L2E, -2.0f));
        const float e2 = ex2(fmaf(x2, L2E, -2.0f));
        const float e3 = ex2(fmaf(x3, L2E, -2.0f));

        // Fill duplicated interleaved rings.
        const float2 v01 = make_float2(e0, e1);
        const float2 v23 = make_float2(e2, e3);
        r01[w][lane] = v01;  r01[w][lane + 32] = v01;
        r23[w][lane] = v23;  r23[w][lane + 32] = v23;
        __syncwarp();

        // Prefetch next iteration's x (overlaps with the pair core below).
        float nx0 = 0.f, nx1 = 0.f, nx2 = 0.f, nx3 = 0.f;
        if (it + 1 < ITERS) {
            const float* nb = logits + ((size_t)(it + 1) * nw + gw) * 128 + lane;
            nx0 = nb[0]; nx1 = nb[32]; nx2 = nb[64]; nx3 = nb[96];
        }

        // Single 16-term product per chain. Offsets 1..15: each unordered
        // pair once; offset 16 only lanes 0..15 (others multiply by 1.0).
        float2 a = r01[w][lane + 1], b = r23[w][lane + 1];
        float p0 = e0 + a.x, p1 = e1 + a.y, p2 = e2 + b.x, p3 = e3 + b.y;
        #pragma unroll
        for (int o = 2; o <= 15; ++o) {
            a = r01[w][lane + o];  b = r23[w][lane + o];
            p0 *= e0 + a.x;  p1 *= e1 + a.y;
            p2 *= e2 + b.x;  p3 *= e3 + b.y;
        }
        a = r01[w][lane + 16];  b = r23[w][lane + 16];
        p0 *= lo16 ? (e0 + a.x) : 1.0f;
        p1 *= lo16 ? (e1 + a.y) : 1.0f;
        p2 *= lo16 ? (e2 + b.x) : 1.0f;
        p3 *= lo16 ? (e3 + b.y) : 1.0f;
        __syncwarp();   // ring reads done before next iteration's refill

        // Per-lane partial: x*CL + x^2*CQ + (log2(prod)+2n)*CLN
        float t0 = fmaf(log2p(p0), CLN, KPS);
        float t1 = fmaf(log2p(p1), CLN, KPS);
        float t2 = fmaf(log2p(p2), CLN, KPS);
        float t3 = fmaf(log2p(p3), CLN, KPS);
        t0 = fmaf(x0, CL, t0);  t0 = fmaf(x0 * x0, CQ, t0);
        t1 = fmaf(x1, CL, t1);  t1 = fmaf(x1 * x1, CQ, t1);
        t2 = fmaf(x2, CL, t2);  t2 = fmaf(x2 * x2, CQ, t2);
        t3 = fmaf(x3, CL, t3);  t3 = fmaf(x3 * x3, CQ, t3);

        // Butterfly reduction: 4 independent scalar chains.
        #pragma unroll
        for (int m = 16; m >= 1; m >>= 1) {
            t0 += __shfl_xor_sync(0xFFFFFFFFu, t0, m);
            t1 += __shfl_xor_sync(0xFFFFFFFFu, t1, m);
            t2 += __shfl_xor_sync(0xFFFFFFFFu, t2, m);
            t3 += __shfl_xor_sync(0xFFFFFFFFu, t3, m);
        }
        if (lane == 0)
            out[it * nw + gw] = make_float4(t0, t1, t2, t3);

        x0 = nx0; x1 = nx1; x2 = nx2; x3 = nx3;
    }
}

extern "C" void kernel_launch(void* const* d_in, const int* in_sizes, int n_in,
                              void* d_out, int out_size)
{
    const float* logits = (const float*)d_in[0];
    float4* out = (float4*)d_out;
    const int n_seg = out_size;                  // 32768 (= 512*4*4*4 exactly)

    rmloss_kernel<<<BLKS, WPB * 32>>>(logits, out, n_seg);
}